// round 16
// baseline (speedup 1.0000x reference)
#include <cuda_runtime.h>
#include <cuda_bf16.h>
#include <cuda_fp16.h>
#include <cstdint>

static constexpr int NN  = 8192;
static constexpr int EE  = 524288;
static constexpr int FIN = 128;
static constexpr int FH  = 256;
static constexpr int FO  = 128;
static constexpr int PAD = 192;   // padded CSR row stride (max degree ~98)

static constexpr int NT128  = NN / 128;
static constexpr int NTILES = NT128 * (NT128 + 1) / 2;  // 2080
static constexpr int DGRID  = 304;                      // 2 CTAs / SM

static constexpr float HSCALE  = 512.0f;    // h  stored as e4m3 * HSCALE * dinv
static constexpr float Z2SCALE = 4096.0f;   // z2 stored as e4m3 * Z2SCALE * dinv
static constexpr float ZSCALE  = 256.0f;    // z  stored as e4m3 * ZSCALE
static constexpr float SIGSCALE = 0.5f / (ZSCALE * ZSCALE);

// ---------------- scratch ----------------------------------------------------
__device__ int g_cursor[NN];       // degree counter; reset inside k_decode
__device__ int g_src[NN * PAD];
__device__ unsigned g_bar;         // decode barrier (monotonic, BSS zero)
__device__ unsigned g_bar2;        // front-end barrier (monotonic, BSS zero)
__device__ __nv_bfloat16 g_w1t[FH * FIN];
__device__ __nv_bfloat16 g_w2t[FO * FH];
__device__ uint16_t      g_h8[NN * 64];    // dinv_n * h[n]  as e4m3 (*HSCALE)
__device__ __nv_bfloat16 g_hab[NN * FIN];  // aggregated h (bf16)
__device__ uint16_t      g_z28[NN * 64];   // dinv_n * z2[n] as e4m3 (*Z2SCALE)
__device__ uint16_t      g_z8[NN * 64];    // z as e4m3 (*ZSCALE)

// ---------------- helpers ------------------------------------------------------
__device__ __forceinline__ uint32_t smem_u32(const void* p) {
    return (uint32_t)__cvta_generic_to_shared(p);
}

__device__ __forceinline__ uint16_t float2_to_fp8x2(float lo, float hi) {
    uint16_t pk;
    asm("cvt.rn.satfinite.e4m3x2.f32 %0, %1, %2;" : "=h"(pk) : "f"(hi), "f"(lo));
    return pk;
}

// 4 fp8 (uint32) -> two f16x2
__device__ __forceinline__ void fp8x4_to_h2x2(uint32_t v, uint32_t& lo2, uint32_t& hi2) {
    asm("{ .reg .b16 lo, hi;\n\t"
        "mov.b32 {lo, hi}, %2;\n\t"
        "cvt.rn.f16x2.e4m3x2 %0, lo;\n\t"
        "cvt.rn.f16x2.e4m3x2 %1, hi; }"
        : "=r"(lo2), "=r"(hi2) : "r"(v));
}

// replay-safe monotonic grid barrier (every launch advances by exactly `grid`)
__device__ __forceinline__ void grid_bar(unsigned* bar, unsigned grid) {
    __syncthreads();
    if (threadIdx.x == 0) {
        __threadfence();
        unsigned tk = atomicAdd(bar, 1u);
        unsigned target = tk - (tk % grid) + grid;
        volatile unsigned* p = bar;
        while (*p < target) { __nanosleep(64); }
    }
    __syncthreads();
    __threadfence();
}

// ---------------- agg sum: unweighted fp8 neighbor+self sum, unroll 8 ----------
__device__ __forceinline__ void agg_sum(const uint32_t* __restrict__ IN,
                                        const int* __restrict__ sidx, int cnt,
                                        int d, int lane,
                                        float& r0, float& r1, float& r2, float& r3,
                                        float& dd) {
    __half2 z = __float2half2_rn(0.f);
    __half2 accA = z, accB = z, accC = z, accD = z;
    int i = 0;
    for (; i + 8 <= cnt; i += 8) {
        int4 sa = *(const int4*)&sidx[i];
        int4 sb = *(const int4*)&sidx[i + 4];
        uint32_t v0 = IN[sa.x * 32 + lane];
        uint32_t v1 = IN[sa.y * 32 + lane];
        uint32_t v2 = IN[sa.z * 32 + lane];
        uint32_t v3 = IN[sa.w * 32 + lane];
        uint32_t v4 = IN[sb.x * 32 + lane];
        uint32_t v5 = IN[sb.y * 32 + lane];
        uint32_t v6 = IN[sb.z * 32 + lane];
        uint32_t v7 = IN[sb.w * 32 + lane];
        uint32_t l, h;
        fp8x4_to_h2x2(v0, l, h); accA = __hadd2(accA, *(__half2*)&l); accB = __hadd2(accB, *(__half2*)&h);
        fp8x4_to_h2x2(v1, l, h); accC = __hadd2(accC, *(__half2*)&l); accD = __hadd2(accD, *(__half2*)&h);
        fp8x4_to_h2x2(v2, l, h); accA = __hadd2(accA, *(__half2*)&l); accB = __hadd2(accB, *(__half2*)&h);
        fp8x4_to_h2x2(v3, l, h); accC = __hadd2(accC, *(__half2*)&l); accD = __hadd2(accD, *(__half2*)&h);
        fp8x4_to_h2x2(v4, l, h); accA = __hadd2(accA, *(__half2*)&l); accB = __hadd2(accB, *(__half2*)&h);
        fp8x4_to_h2x2(v5, l, h); accC = __hadd2(accC, *(__half2*)&l); accD = __hadd2(accD, *(__half2*)&h);
        fp8x4_to_h2x2(v6, l, h); accA = __hadd2(accA, *(__half2*)&l); accB = __hadd2(accB, *(__half2*)&h);
        fp8x4_to_h2x2(v7, l, h); accC = __hadd2(accC, *(__half2*)&l); accD = __hadd2(accD, *(__half2*)&h);
    }
    for (; i < cnt; i++) {
        uint32_t v = IN[sidx[i] * 32 + lane];
        uint32_t l, h;
        fp8x4_to_h2x2(v, l, h);
        accA = __hadd2(accA, *(__half2*)&l);
        accB = __hadd2(accB, *(__half2*)&h);
    }
    // self term (row already scaled by own dinv)
    {
        uint32_t v = IN[d * 32 + lane];
        uint32_t l, h;
        fp8x4_to_h2x2(v, l, h);
        accA = __hadd2(accA, *(__half2*)&l);
        accB = __hadd2(accB, *(__half2*)&h);
    }
    float2 s01 = __half22float2(__hadd2(accA, accC));
    float2 s23 = __half22float2(__hadd2(accB, accD));
    r0 = s01.x; r1 = s01.y; r2 = s23.x; r3 = s23.y;
    dd = rsqrtf((float)cnt + 1.0f);
}

// ---------------- fused front-end: wconv+fill | gather | agg0 -------------------
__global__ void __launch_bounds__(256) k_front(const int* __restrict__ x,
                                               const float* __restrict__ emb,
                                               const float* __restrict__ W1,
                                               const float* __restrict__ W2,
                                               const int* __restrict__ src,
                                               const int* __restrict__ dst) {
    __shared__ int sidx[8][PAD];
    int t = threadIdx.x;
    int gid = blockIdx.x * 256 + t;        // 0 .. 77823

    // ---- phase A: weight transpose + padded CSR fill ----
    if (gid < FH * FIN + FO * FH) {        // 65536 weight elements
        if (gid < FH * FIN) {
            int j = gid >> 7, k = gid & 127;
            g_w1t[gid] = __float2bfloat16(W1[k * FH + j]);
        } else {
            int i2 = gid - FH * FIN;
            int j = i2 >> 8, k = i2 & 255;
            g_w2t[i2] = __float2bfloat16(W2[k * FO + j]);
        }
    }
    if (gid < EE / 8) {                    // 65536 fill chunks, 8 edges each
        int e = gid * 8;
        int4 d0 = *(const int4*)(dst + e);
        int4 d1 = *(const int4*)(dst + e + 4);
        int4 s0 = *(const int4*)(src + e);
        int4 s1 = *(const int4*)(src + e + 4);
        int p0 = atomicAdd(&g_cursor[d0.x], 1);
        int p1 = atomicAdd(&g_cursor[d0.y], 1);
        int p2 = atomicAdd(&g_cursor[d0.z], 1);
        int p3 = atomicAdd(&g_cursor[d0.w], 1);
        int p4 = atomicAdd(&g_cursor[d1.x], 1);
        int p5 = atomicAdd(&g_cursor[d1.y], 1);
        int p6 = atomicAdd(&g_cursor[d1.z], 1);
        int p7 = atomicAdd(&g_cursor[d1.w], 1);
        g_src[d0.x * PAD + p0] = s0.x;
        g_src[d0.y * PAD + p1] = s0.y;
        g_src[d0.z * PAD + p2] = s0.z;
        g_src[d0.w * PAD + p3] = s0.w;
        g_src[d1.x * PAD + p4] = s1.x;
        g_src[d1.y * PAD + p5] = s1.y;
        g_src[d1.z * PAD + p6] = s1.z;
        g_src[d1.w * PAD + p7] = s1.w;
    }
    grid_bar(&g_bar2, DGRID);

    // ---- phase B: embedding gather, pre-scaled by dinv ----
    for (int idx = gid; idx < NN * 64; idx += DGRID * 256) {
        int n = idx >> 6, c = idx & 63;
        float dv = rsqrtf((float)g_cursor[n] + 1.0f) * HSCALE;
        float2 f = *(const float2*)(emb + (size_t)x[n] * FIN + c * 2);
        g_h8[n * 64 + c] = float2_to_fp8x2(f.x * dv, f.y * dv);
    }
    grid_bar(&g_bar2, DGRID);

    // ---- phase C: layer-1 aggregation, warp-per-node strided ----
    int w = t >> 5, lane = t & 31;
    const uint32_t* IN = (const uint32_t*)g_h8;
    for (int d = blockIdx.x * 8 + w; d < NN; d += DGRID * 8) {
        int cnt = g_cursor[d];
        const int* rowp = g_src + d * PAD;
        for (int i = lane; i < cnt; i += 32) sidx[w][i] = rowp[i];
        __syncwarp();
        float r0, r1, r2, r3, dd;
        agg_sum(IN, sidx[w], cnt, d, lane, r0, r1, r2, r3, dd);
        float k = dd * (1.0f / HSCALE);
        __nv_bfloat162 b0 = __floats2bfloat162_rn(r0 * k, r1 * k);
        __nv_bfloat162 b1 = __floats2bfloat162_rn(r2 * k, r3 * k);
        *(uint2*)&g_hab[(size_t)d * FIN + lane * 4] =
            make_uint2(*(uint32_t*)&b0, *(uint32_t*)&b1);
        __syncwarp();
    }
}

// ---------------- mma helpers ---------------------------------------------------
__device__ __forceinline__ void ldmat4(uint32_t* r, const void* p) {
    asm volatile("ldmatrix.sync.aligned.m8n8.x4.shared.b16 {%0,%1,%2,%3}, [%4];"
                 : "=r"(r[0]), "=r"(r[1]), "=r"(r[2]), "=r"(r[3])
                 : "r"(smem_u32(p)));
}

__device__ __forceinline__ void mma16816(float* c, const uint32_t* a, const uint32_t* b) {
    asm volatile("mma.sync.aligned.m16n8k16.row.col.f32.bf16.bf16.f32 "
                 "{%0,%1,%2,%3}, {%4,%5,%6,%7}, {%8,%9}, {%0,%1,%2,%3};"
                 : "+f"(c[0]), "+f"(c[1]), "+f"(c[2]), "+f"(c[3])
                 : "r"(a[0]), "r"(a[1]), "r"(a[2]), "r"(a[3]), "r"(b[0]), "r"(b[1]));
}

__device__ __forceinline__ void mma16832f8(float* c, const uint32_t* a, const uint32_t* b) {
    asm volatile("mma.sync.aligned.m16n8k32.row.col.f32.e4m3.e4m3.f32 "
                 "{%0,%1,%2,%3}, {%4,%5,%6,%7}, {%8,%9}, {%0,%1,%2,%3};"
                 : "+f"(c[0]), "+f"(c[1]), "+f"(c[2]), "+f"(c[3])
                 : "r"(a[0]), "r"(a[1]), "r"(a[2]), "r"(a[3]), "r"(b[0]), "r"(b[1]));
}

__device__ __forceinline__ void cpa16(void* sdst, const void* gsrc) {
    asm volatile("cp.async.cg.shared.global [%0], [%1], 16;"
                 :: "r"(smem_u32(sdst)), "l"(gsrc) : "memory");
}

// ---------------- fused lin: z2 = relu(hab@W1+b1) @ W2, fp8*dinv out -----------
static constexpr int LIN_SMEM = (64 * 136 + 256 * 136 + 64 * 264 + 128 * 264) * 2; // 188416

__global__ void __launch_bounds__(256) k_lin(const float* __restrict__ b1) {
    constexpr int P1 = 136, P2 = 264;
    extern __shared__ __nv_bfloat16 smL[];
    __nv_bfloat16* sA1 = smL;
    __nv_bfloat16* sW1 = smL + 64 * P1;
    __nv_bfloat16* sA2 = sW1 + 256 * P1;
    __nv_bfloat16* sW2 = sA2 + 64 * P2;

    int t = threadIdx.x;
    int n0 = blockIdx.x * 64;

    for (int v = t; v < 1024; v += 256) {
        int r = v >> 4, m = v & 15;
        cpa16(sA1 + r * P1 + m * 8, g_hab + (size_t)(n0 + r) * FIN + m * 8);
    }
    for (int v = t; v < 4096; v += 256) {
        int r = v >> 4, m = v & 15;
        cpa16(sW1 + r * P1 + m * 8, g_w1t + r * FIN + m * 8);
    }
    asm volatile("cp.async.commit_group;" ::: "memory");
    for (int v = t; v < 4096; v += 256) {
        int r = v >> 5, m = v & 31;
        cpa16(sW2 + r * P2 + m * 8, g_w2t + r * FH + m * 8);
    }
    asm volatile("cp.async.commit_group;" ::: "memory");

    int lane = t & 31, w = t >> 5;

    asm volatile("cp.async.wait_group 1;" ::: "memory");
    __syncthreads();
    {
        int wm = (w & 1) * 32, wn = (w >> 1) * 64;
        float acc[2][8][4] = {};
#pragma unroll
        for (int ks = 0; ks < 8; ks++) {
            int k0 = ks * 16;
            uint32_t a[2][4], b[8][2];
#pragma unroll
            for (int mt = 0; mt < 2; mt++)
                ldmat4(a[mt], sA1 + (wm + mt * 16 + (lane & 15)) * P1 + k0 + (lane >> 4) * 8);
#pragma unroll
            for (int pr = 0; pr < 4; pr++) {
                uint32_t r4[4];
                ldmat4(r4, sW1 + (wn + pr * 16 + (lane >> 4) * 8 + (lane & 7)) * P1
                             + k0 + ((lane >> 3) & 1) * 8);
                b[2 * pr][0] = r4[0]; b[2 * pr][1] = r4[1];
                b[2 * pr + 1][0] = r4[2]; b[2 * pr + 1][1] = r4[3];
            }
#pragma unroll
            for (int mt = 0; mt < 2; mt++)
#pragma unroll
                for (int nt = 0; nt < 8; nt++) mma16816(acc[mt][nt], a[mt], b[nt]);
        }
#pragma unroll
        for (int mt = 0; mt < 2; mt++) {
            int row = wm + mt * 16 + (lane >> 2);
#pragma unroll
            for (int nt = 0; nt < 8; nt++) {
                int col = wn + nt * 8 + (lane & 3) * 2;
                float2 bb = *(const float2*)(b1 + col);
                float v0 = fmaxf(acc[mt][nt][0] + bb.x, 0.f);
                float v1 = fmaxf(acc[mt][nt][1] + bb.y, 0.f);
                float v2 = fmaxf(acc[mt][nt][2] + bb.x, 0.f);
                float v3 = fmaxf(acc[mt][nt][3] + bb.y, 0.f);
                *(__nv_bfloat162*)&sA2[row * P2 + col]       = __floats2bfloat162_rn(v0, v1);
                *(__nv_bfloat162*)&sA2[(row + 8) * P2 + col] = __floats2bfloat162_rn(v2, v3);
            }
        }
    }
    asm volatile("cp.async.wait_group 0;" ::: "memory");
    __syncthreads();

    {
        int wm = (w & 1) * 32, wn = (w >> 1) * 32;
        float acc[2][4][4] = {};
#pragma unroll
        for (int ks = 0; ks < 16; ks++) {
            int k0 = ks * 16;
            uint32_t a[2][4], b[4][2];
#pragma unroll
            for (int mt = 0; mt < 2; mt++)
                ldmat4(a[mt], sA2 + (wm + mt * 16 + (lane & 15)) * P2 + k0 + (lane >> 4) * 8);
#pragma unroll
            for (int pr = 0; pr < 2; pr++) {
                uint32_t r4[4];
                ldmat4(r4, sW2 + (wn + pr * 16 + (lane >> 4) * 8 + (lane & 7)) * P2
                             + k0 + ((lane >> 3) & 1) * 8);
                b[2 * pr][0] = r4[0]; b[2 * pr][1] = r4[1];
                b[2 * pr + 1][0] = r4[2]; b[2 * pr + 1][1] = r4[3];
            }
#pragma unroll
            for (int mt = 0; mt < 2; mt++)
#pragma unroll
                for (int nt = 0; nt < 4; nt++) mma16816(acc[mt][nt], a[mt], b[nt]);
        }
#pragma unroll
        for (int mt = 0; mt < 2; mt++) {
            int row = wm + mt * 16 + (lane >> 2);
            float dva = rsqrtf((float)g_cursor[n0 + row] + 1.0f) * Z2SCALE;
            float dvb = rsqrtf((float)g_cursor[n0 + row + 8] + 1.0f) * Z2SCALE;
#pragma unroll
            for (int nt = 0; nt < 4; nt++) {
                int col = wn + nt * 8 + (lane & 3) * 2;
                g_z28[(size_t)(n0 + row) * 64 + (col >> 1)] =
                    float2_to_fp8x2(acc[mt][nt][0] * dva, acc[mt][nt][1] * dva);
                g_z28[(size_t)(n0 + row + 8) * 64 + (col >> 1)] =
                    float2_to_fp8x2(acc[mt][nt][2] * dvb, acc[mt][nt][3] * dvb);
            }
        }
    }
}

// ---------------- decode: agg2 phase + grid barrier + persistent fp8 mma --------
__device__ __forceinline__ float sigmoidf_(float v) {
    float th;
    asm("tanh.approx.f32 %0, %1;" : "=f"(th) : "f"(v * SIGSCALE));
    return fmaf(th, 0.5f, 0.5f);
}

__device__ __forceinline__ void bulk_store_row(void* gptr, uint32_t saddr, int bytes) {
    asm volatile("cp.async.bulk.global.shared::cta.bulk_group [%0], [%1], %2;"
                 :: "l"(gptr), "r"(saddr), "r"(bytes) : "memory");
}

__device__ __forceinline__ void tile_coords(int idx, int& bi, int& bj) {
    float fb = 64.5f - sqrtf(64.5f * 64.5f - 2.0f * (float)idx);
    int b = (int)fb;
    if (b < 0) b = 0;
    while (b > 0 && (b * 64 - b * (b - 1) / 2) > idx) b--;
    while (((b + 1) * 64 - (b + 1) * b / 2) <= idx) b++;
    bi = b;
    bj = b + (idx - (b * 64 - b * (b - 1) / 2));
}

static constexpr int STG_SZ   = 128 * 136 * 4;      // 69632
static constexpr int ZB_OFF   = STG_SZ;
static constexpr int ZT_SZ    = 128 * 144;          // 18432
static constexpr int DEC_SMEM = STG_SZ + 2 * ZT_SZ; // 106496 -> 2 CTAs/SM

__global__ void __launch_bounds__(256, 2) k_decode(const float* __restrict__ bias,
                                                   float* __restrict__ out) {
    extern __shared__ char smb[];
    int t = threadIdx.x;
    int lane = t & 31, w = t >> 5;
    int wm = (w & 3) * 32;
    int wn = (w >> 2) * 64;
    constexpr int PU = 72;
    constexpr int PF = 136;

    // ---- phase 0: layer-2 aggregation (warp-per-node, strided) ----
    {
        int* sidx = (int*)smb + w * PAD;           // staging in sf area
        float4 bb = *(const float4*)(bias + lane * 4);
        for (int d = blockIdx.x * 8 + w; d < NN; d += DGRID * 8) {
            int cnt = g_cursor[d];
            const int* rowp = g_src + d * PAD;
            for (int i = lane; i < cnt; i += 32) sidx[i] = rowp[i];
            __syncwarp();
            float r0, r1, r2, r3, dd;
            agg_sum((const uint32_t*)g_z28, sidx, cnt, d, lane, r0, r1, r2, r3, dd);
            float k = dd * (ZSCALE / Z2SCALE);
            float o0 = fmaf(r0, k, bb.x * ZSCALE);
            float o1 = fmaf(r1, k, bb.y * ZSCALE);
            float o2 = fmaf(r2, k, bb.z * ZSCALE);
            float o3 = fmaf(r3, k, bb.w * ZSCALE);
            uint16_t p0 = float2_to_fp8x2(o0, o1);
            uint16_t p1 = float2_to_fp8x2(o2, o3);
            ((uint32_t*)g_z8)[d * 32 + lane] = (uint32_t)p0 | ((uint32_t)p1 << 16);
            __syncwarp();
        }
    }

    grid_bar(&g_bar, DGRID);

    // reset CSR cursors for the next replay (safe: all agg reads done)
    if (blockIdx.x < 32) g_cursor[blockIdx.x * 256 + t] = 0;

    float* sf = (float*)smb;
    const __nv_bfloat16* zA = (const __nv_bfloat16*)(smb + ZB_OFF);
    const __nv_bfloat16* zB = zA + ZT_SZ / 2;

    for (int idx = blockIdx.x; idx < NTILES; idx += DGRID) {
        int bi, bj;
        tile_coords(idx, bi, bj);
        int i0 = bi * 128, j0 = bj * 128;
        bool diag = (bi == bj);

        {
            const char* Z = (const char*)g_z8;
#pragma unroll
            for (int k = 0; k < 8; k++) {
                int v = t + k * 256;
                int which = v >> 10;
                int r = (v >> 3) & 127;
                int c = (v & 7) * 16;
                const char* srcp = Z + (((size_t)((which ? j0 : i0) + r)) << 7) + c;
                uint32_t dstp = smem_u32(smb + ZB_OFF + which * ZT_SZ + r * 144 + c);
                asm volatile("cp.async.cg.shared.global [%0], [%1], 16;"
                             :: "r"(dstp), "l"(srcp) : "memory");
            }
        }
        asm volatile("cp.async.commit_group;" ::: "memory");
        asm volatile("cp.async.wait_group 0;" ::: "memory");
        __syncthreads();

        float acc[2][8][4] = {};
#pragma unroll
        for (int ks = 0; ks < 4; ks++) {
            int k0 = ks * 16;
            uint32_t a[2][4], b[8][2];
#pragma unroll
            for (int mt = 0; mt < 2; mt++)
                ldmat4(a[mt], zA + (wm + mt * 16 + (lane & 15)) * PU + k0 + (lane >> 4) * 8);
#pragma unroll
            for (int pr = 0; pr < 4; pr++) {
                uint32_t r4[4];
                ldmat4(r4, zB + (wn + pr * 16 + (lane >> 4) * 8 + (lane & 7)) * PU
                             + k0 + ((lane >> 3) & 1) * 8);
                b[2 * pr][0] = r4[0]; b[2 * pr][1] = r4[1];
                b[2 * pr + 1][0] = r4[2]; b[2 * pr + 1][1] = r4[3];
            }
#pragma unroll
            for (int mt = 0; mt < 2; mt++)
#pragma unroll
                for (int nt = 0; nt < 8; nt++) mma16832f8(acc[mt][nt], a[mt], b[nt]);
        }

#pragma unroll
        for (int mt = 0; mt < 2; mt++)
#pragma unroll
            for (int nt = 0; nt < 8; nt++)
#pragma unroll
                for (int q = 0; q < 4; q++) acc[mt][nt][q] = sigmoidf_(acc[mt][nt][q]);

        int r0b = wm + (lane >> 2);

        // pass 1: direct tile
        asm volatile("cp.async.bulk.wait_group.read 0;" ::: "memory");
        __syncthreads();
#pragma unroll
        for (int mt = 0; mt < 2; mt++) {
            int r0 = r0b + mt * 16;
#pragma unroll
            for (int nt = 0; nt < 8; nt++) {
                int c0 = wn + nt * 8 + (lane & 3) * 2;
                *(float2*)&sf[r0 * PF + c0] =
                    make_float2(acc[mt][nt][0], acc[mt][nt][1]);
                *(float2*)&sf[(r0 + 8) * PF + c0] =
                    make_float2(acc[mt][nt][2], acc[mt][nt][3]);
            }
        }
        __syncthreads();
        if (t < 128) {
            asm volatile("fence.proxy.async.shared::cta;" ::: "memory");
            bulk_store_row(out + (size_t)(i0 + t) * NN + j0, smem_u32(&sf[t * PF]), 512);
            asm volatile("cp.async.bulk.commit_group;" ::: "memory");
        }

        // pass 2: mirror tile (transposed)
        if (!diag) {
            asm volatile("cp.async.bulk.wait_group.read 0;" ::: "memory");
            __syncthreads();
#pragma unroll
            for (int mt = 0; mt < 2; mt++) {
                int r0 = r0b + mt * 16;
#pragma unroll
                for (int nt = 0; nt < 8; nt++) {
                    int c0 = wn + nt * 8 + (lane & 3) * 2;
                    sf[c0 * PF + r0]           = acc[mt][nt][0];
                    sf[(c0 + 1) * PF + r0]     = acc[mt][nt][1];
                    sf[c0 * PF + r0 + 8]       = acc[mt][nt][2];
                    sf[(c0 + 1) * PF + r0 + 8] = acc[mt][nt][3];
                }
            }
            __syncthreads();
            if (t < 128) {
                asm volatile("fence.proxy.async.shared::cta;" ::: "memory");
                bulk_store_row(out + (size_t)(j0 + t) * NN + i0, smem_u32(&sf[t * PF]), 512);
                asm volatile("cp.async.bulk.commit_group;" ::: "memory");
            }
        }
    }

    asm volatile("cp.async.bulk.wait_group 0;" ::: "memory");
}

// ---------------- launch ----------------------------------------------------------
extern "C" void kernel_launch(void* const* d_in, const int* in_sizes, int n_in,
                              void* d_out, int out_size) {
    const int*   x   = (const int*)d_in[0];
    const int*   ei  = (const int*)d_in[1];
    const float* emb = (const float*)d_in[2];
    const float* W1  = (const float*)d_in[3];
    const float* b1  = (const float*)d_in[4];
    const float* W2  = (const float*)d_in[5];
    const float* b2  = (const float*)d_in[6];
    float* out = (float*)d_out;

    const int* src = ei;
    const int* dst = ei + EE;

    cudaFuncSetAttribute(k_decode, cudaFuncAttributeMaxDynamicSharedMemorySize, DEC_SMEM);
    cudaFuncSetAttribute(k_lin,    cudaFuncAttributeMaxDynamicSharedMemorySize, LIN_SMEM);

    k_front <<<DGRID, 256>>>(x, emb, W1, W2, src, dst);
    k_lin   <<<NN / 64, 256, LIN_SMEM>>>(b1);
    k_decode<<<DGRID, 256, DEC_SMEM>>>(b2, out);
}

// round 17
// speedup vs baseline: 1.0321x; 1.0321x over previous
#include <cuda_runtime.h>
#include <cuda_bf16.h>
#include <cuda_fp16.h>
#include <cstdint>

static constexpr int NN  = 8192;
static constexpr int EE  = 524288;
static constexpr int FIN = 128;
static constexpr int FH  = 256;
static constexpr int FO  = 128;
static constexpr int PAD = 192;   // padded CSR row stride (max degree ~98)

static constexpr int NT128  = NN / 128;
static constexpr int NTILES = NT128 * (NT128 + 1) / 2;  // 2080
static constexpr int DGRID  = 304;                      // 2 CTAs / SM

static constexpr float HSCALE  = 512.0f;    // h  stored as e4m3 * HSCALE * dinv
static constexpr float Z2SCALE = 4096.0f;   // z2 stored as e4m3 * Z2SCALE * dinv
static constexpr float ZSCALE  = 256.0f;    // z  stored as e4m3 * ZSCALE
static constexpr float SIGSCALE = 0.5f / (ZSCALE * ZSCALE);

// ---------------- scratch ----------------------------------------------------
__device__ int g_cursor[NN];       // degree counter; reset inside k_decode
__device__ int g_src[NN * PAD];
__device__ unsigned g_bar;         // decode barrier (monotonic, BSS zero)
__device__ unsigned g_tk;          // decode tile tickets (monotonic, BSS zero)
__device__ __nv_bfloat16 g_w1t[FH * FIN];
__device__ __nv_bfloat16 g_w2t[FO * FH];
__device__ uint16_t      g_h8[NN * 64];    // dinv_n * h[n]  as e4m3 (*HSCALE)
__device__ __nv_bfloat16 g_hab[NN * FIN];  // aggregated h (bf16)
__device__ uint16_t      g_z28[NN * 64];   // dinv_n * z2[n] as e4m3 (*Z2SCALE)
__device__ uint16_t      g_z8[NN * 64];    // z as e4m3 (*ZSCALE)

// ---------------- helpers ------------------------------------------------------
__device__ __forceinline__ uint32_t smem_u32(const void* p) {
    return (uint32_t)__cvta_generic_to_shared(p);
}

__device__ __forceinline__ uint16_t float2_to_fp8x2(float lo, float hi) {
    uint16_t pk;
    asm("cvt.rn.satfinite.e4m3x2.f32 %0, %1, %2;" : "=h"(pk) : "f"(hi), "f"(lo));
    return pk;
}

// 4 fp8 (uint32) -> two f16x2
__device__ __forceinline__ void fp8x4_to_h2x2(uint32_t v, uint32_t& lo2, uint32_t& hi2) {
    asm("{ .reg .b16 lo, hi;\n\t"
        "mov.b32 {lo, hi}, %2;\n\t"
        "cvt.rn.f16x2.e4m3x2 %0, lo;\n\t"
        "cvt.rn.f16x2.e4m3x2 %1, hi; }"
        : "=r"(lo2), "=r"(hi2) : "r"(v));
}

// ---------------- prep: wconv | CSR fill ----------------------------------------
__global__ void k_prep(const float* __restrict__ W1, const float* __restrict__ W2,
                       const int* __restrict__ src, const int* __restrict__ dst) {
    int b = blockIdx.x;
    if (b < 256) {                        // weight transpose + bf16
        int idx = b * 256 + threadIdx.x;
        if (idx < FH * FIN) {
            int j = idx >> 7, k = idx & 127;
            g_w1t[idx] = __float2bfloat16(W1[k * FH + j]);
        } else {
            int i2 = idx - FH * FIN;
            int j = i2 >> 8, k = i2 & 255;
            g_w2t[i2] = __float2bfloat16(W2[k * FO + j]);
        }
    } else {                              // padded CSR fill, 8 edges/thread
        int e = ((b - 256) * 256 + threadIdx.x) * 8;
        int4 d0 = *(const int4*)(dst + e);
        int4 d1 = *(const int4*)(dst + e + 4);
        int4 s0 = *(const int4*)(src + e);
        int4 s1 = *(const int4*)(src + e + 4);
        int p0 = atomicAdd(&g_cursor[d0.x], 1);
        int p1 = atomicAdd(&g_cursor[d0.y], 1);
        int p2 = atomicAdd(&g_cursor[d0.z], 1);
        int p3 = atomicAdd(&g_cursor[d0.w], 1);
        int p4 = atomicAdd(&g_cursor[d1.x], 1);
        int p5 = atomicAdd(&g_cursor[d1.y], 1);
        int p6 = atomicAdd(&g_cursor[d1.z], 1);
        int p7 = atomicAdd(&g_cursor[d1.w], 1);
        g_src[d0.x * PAD + p0] = s0.x;
        g_src[d0.y * PAD + p1] = s0.y;
        g_src[d0.z * PAD + p2] = s0.z;
        g_src[d0.w * PAD + p3] = s0.w;
        g_src[d1.x * PAD + p4] = s1.x;
        g_src[d1.y * PAD + p5] = s1.y;
        g_src[d1.z * PAD + p6] = s1.z;
        g_src[d1.w * PAD + p7] = s1.w;
    }
}

// ---------------- embedding gather, pre-scaled by dinv --------------------------
__global__ void k_gather(const int* __restrict__ x, const float* __restrict__ emb) {
    int idx = blockIdx.x * 256 + threadIdx.x;   // NN*64 threads
    int n = idx >> 6, t = idx & 63;
    float dv = rsqrtf((float)g_cursor[n] + 1.0f) * HSCALE;
    float2 f = *(const float2*)(emb + (size_t)x[n] * FIN + t * 2);
    g_h8[n * 64 + t] = float2_to_fp8x2(f.x * dv, f.y * dv);
}

// ---------------- agg sum: unweighted fp8 neighbor+self sum, unroll 8 ----------
__device__ __forceinline__ void agg_sum(const uint32_t* __restrict__ IN,
                                        const int* __restrict__ sidx, int cnt,
                                        int d, int lane,
                                        float& r0, float& r1, float& r2, float& r3,
                                        float& dd) {
    __half2 z = __float2half2_rn(0.f);
    __half2 accA = z, accB = z, accC = z, accD = z;
    int i = 0;
    for (; i + 8 <= cnt; i += 8) {
        int4 sa = *(const int4*)&sidx[i];
        int4 sb = *(const int4*)&sidx[i + 4];
        uint32_t v0 = IN[sa.x * 32 + lane];
        uint32_t v1 = IN[sa.y * 32 + lane];
        uint32_t v2 = IN[sa.z * 32 + lane];
        uint32_t v3 = IN[sa.w * 32 + lane];
        uint32_t v4 = IN[sb.x * 32 + lane];
        uint32_t v5 = IN[sb.y * 32 + lane];
        uint32_t v6 = IN[sb.z * 32 + lane];
        uint32_t v7 = IN[sb.w * 32 + lane];
        uint32_t l, h;
        fp8x4_to_h2x2(v0, l, h); accA = __hadd2(accA, *(__half2*)&l); accB = __hadd2(accB, *(__half2*)&h);
        fp8x4_to_h2x2(v1, l, h); accC = __hadd2(accC, *(__half2*)&l); accD = __hadd2(accD, *(__half2*)&h);
        fp8x4_to_h2x2(v2, l, h); accA = __hadd2(accA, *(__half2*)&l); accB = __hadd2(accB, *(__half2*)&h);
        fp8x4_to_h2x2(v3, l, h); accC = __hadd2(accC, *(__half2*)&l); accD = __hadd2(accD, *(__half2*)&h);
        fp8x4_to_h2x2(v4, l, h); accA = __hadd2(accA, *(__half2*)&l); accB = __hadd2(accB, *(__half2*)&h);
        fp8x4_to_h2x2(v5, l, h); accC = __hadd2(accC, *(__half2*)&l); accD = __hadd2(accD, *(__half2*)&h);
        fp8x4_to_h2x2(v6, l, h); accA = __hadd2(accA, *(__half2*)&l); accB = __hadd2(accB, *(__half2*)&h);
        fp8x4_to_h2x2(v7, l, h); accC = __hadd2(accC, *(__half2*)&l); accD = __hadd2(accD, *(__half2*)&h);
    }
    for (; i < cnt; i++) {
        uint32_t v = IN[sidx[i] * 32 + lane];
        uint32_t l, h;
        fp8x4_to_h2x2(v, l, h);
        accA = __hadd2(accA, *(__half2*)&l);
        accB = __hadd2(accB, *(__half2*)&h);
    }
    // self term (row already scaled by own dinv)
    {
        uint32_t v = IN[d * 32 + lane];
        uint32_t l, h;
        fp8x4_to_h2x2(v, l, h);
        accA = __hadd2(accA, *(__half2*)&l);
        accB = __hadd2(accB, *(__half2*)&h);
    }
    float2 s01 = __half22float2(__hadd2(accA, accC));
    float2 s23 = __half22float2(__hadd2(accB, accD));
    r0 = s01.x; r1 = s01.y; r2 = s23.x; r3 = s23.y;
    dd = rsqrtf((float)cnt + 1.0f);
}

// ---------------- layer-1 pre-aggregation: warp-per-node ------------------------
__global__ void __launch_bounds__(32) k_agg0() {
    __shared__ int sidx[PAD];
    int d = blockIdx.x, lane = threadIdx.x;
    int cnt = g_cursor[d];
    const int* rowp = g_src + d * PAD;
    for (int i = lane; i < cnt; i += 32) sidx[i] = rowp[i];
    __syncwarp();
    float r0, r1, r2, r3, dd;
    agg_sum((const uint32_t*)g_h8, sidx, cnt, d, lane, r0, r1, r2, r3, dd);
    float k = dd * (1.0f / HSCALE);
    __nv_bfloat162 b0 = __floats2bfloat162_rn(r0 * k, r1 * k);
    __nv_bfloat162 b1 = __floats2bfloat162_rn(r2 * k, r3 * k);
    *(uint2*)&g_hab[(size_t)d * FIN + lane * 4] =
        make_uint2(*(uint32_t*)&b0, *(uint32_t*)&b1);
}

// ---------------- mma helpers ---------------------------------------------------
__device__ __forceinline__ void ldmat4(uint32_t* r, const void* p) {
    asm volatile("ldmatrix.sync.aligned.m8n8.x4.shared.b16 {%0,%1,%2,%3}, [%4];"
                 : "=r"(r[0]), "=r"(r[1]), "=r"(r[2]), "=r"(r[3])
                 : "r"(smem_u32(p)));
}

__device__ __forceinline__ void mma16816(float* c, const uint32_t* a, const uint32_t* b) {
    asm volatile("mma.sync.aligned.m16n8k16.row.col.f32.bf16.bf16.f32 "
                 "{%0,%1,%2,%3}, {%4,%5,%6,%7}, {%8,%9}, {%0,%1,%2,%3};"
                 : "+f"(c[0]), "+f"(c[1]), "+f"(c[2]), "+f"(c[3])
                 : "r"(a[0]), "r"(a[1]), "r"(a[2]), "r"(a[3]), "r"(b[0]), "r"(b[1]));
}

__device__ __forceinline__ void mma16832f8(float* c, const uint32_t* a, const uint32_t* b) {
    asm volatile("mma.sync.aligned.m16n8k32.row.col.f32.e4m3.e4m3.f32 "
                 "{%0,%1,%2,%3}, {%4,%5,%6,%7}, {%8,%9}, {%0,%1,%2,%3};"
                 : "+f"(c[0]), "+f"(c[1]), "+f"(c[2]), "+f"(c[3])
                 : "r"(a[0]), "r"(a[1]), "r"(a[2]), "r"(a[3]), "r"(b[0]), "r"(b[1]));
}

__device__ __forceinline__ void cpa16(void* sdst, const void* gsrc) {
    asm volatile("cp.async.cg.shared.global [%0], [%1], 16;"
                 :: "r"(smem_u32(sdst)), "l"(gsrc) : "memory");
}

// ---------------- fused lin: z2 = relu(hab@W1+b1) @ W2, fp8*dinv out -----------
static constexpr int LIN_SMEM = (64 * 136 + 256 * 136 + 64 * 264 + 128 * 264) * 2; // 188416

__global__ void __launch_bounds__(256) k_lin(const float* __restrict__ b1) {
    constexpr int P1 = 136, P2 = 264;
    extern __shared__ __nv_bfloat16 smL[];
    __nv_bfloat16* sA1 = smL;
    __nv_bfloat16* sW1 = smL + 64 * P1;
    __nv_bfloat16* sA2 = sW1 + 256 * P1;
    __nv_bfloat16* sW2 = sA2 + 64 * P2;

    int t = threadIdx.x;
    int n0 = blockIdx.x * 64;

    for (int v = t; v < 1024; v += 256) {
        int r = v >> 4, m = v & 15;
        cpa16(sA1 + r * P1 + m * 8, g_hab + (size_t)(n0 + r) * FIN + m * 8);
    }
    for (int v = t; v < 4096; v += 256) {
        int r = v >> 4, m = v & 15;
        cpa16(sW1 + r * P1 + m * 8, g_w1t + r * FIN + m * 8);
    }
    asm volatile("cp.async.commit_group;" ::: "memory");
    for (int v = t; v < 4096; v += 256) {
        int r = v >> 5, m = v & 31;
        cpa16(sW2 + r * P2 + m * 8, g_w2t + r * FH + m * 8);
    }
    asm volatile("cp.async.commit_group;" ::: "memory");

    int lane = t & 31, w = t >> 5;

    asm volatile("cp.async.wait_group 1;" ::: "memory");
    __syncthreads();
    {
        int wm = (w & 1) * 32, wn = (w >> 1) * 64;
        float acc[2][8][4] = {};
#pragma unroll
        for (int ks = 0; ks < 8; ks++) {
            int k0 = ks * 16;
            uint32_t a[2][4], b[8][2];
#pragma unroll
            for (int mt = 0; mt < 2; mt++)
                ldmat4(a[mt], sA1 + (wm + mt * 16 + (lane & 15)) * P1 + k0 + (lane >> 4) * 8);
#pragma unroll
            for (int pr = 0; pr < 4; pr++) {
                uint32_t r4[4];
                ldmat4(r4, sW1 + (wn + pr * 16 + (lane >> 4) * 8 + (lane & 7)) * P1
                             + k0 + ((lane >> 3) & 1) * 8);
                b[2 * pr][0] = r4[0]; b[2 * pr][1] = r4[1];
                b[2 * pr + 1][0] = r4[2]; b[2 * pr + 1][1] = r4[3];
            }
#pragma unroll
            for (int mt = 0; mt < 2; mt++)
#pragma unroll
                for (int nt = 0; nt < 8; nt++) mma16816(acc[mt][nt], a[mt], b[nt]);
        }
#pragma unroll
        for (int mt = 0; mt < 2; mt++) {
            int row = wm + mt * 16 + (lane >> 2);
#pragma unroll
            for (int nt = 0; nt < 8; nt++) {
                int col = wn + nt * 8 + (lane & 3) * 2;
                float2 bb = *(const float2*)(b1 + col);
                float v0 = fmaxf(acc[mt][nt][0] + bb.x, 0.f);
                float v1 = fmaxf(acc[mt][nt][1] + bb.y, 0.f);
                float v2 = fmaxf(acc[mt][nt][2] + bb.x, 0.f);
                float v3 = fmaxf(acc[mt][nt][3] + bb.y, 0.f);
                *(__nv_bfloat162*)&sA2[row * P2 + col]       = __floats2bfloat162_rn(v0, v1);
                *(__nv_bfloat162*)&sA2[(row + 8) * P2 + col] = __floats2bfloat162_rn(v2, v3);
            }
        }
    }
    asm volatile("cp.async.wait_group 0;" ::: "memory");
    __syncthreads();

    {
        int wm = (w & 1) * 32, wn = (w >> 1) * 32;
        float acc[2][4][4] = {};
#pragma unroll
        for (int ks = 0; ks < 16; ks++) {
            int k0 = ks * 16;
            uint32_t a[2][4], b[4][2];
#pragma unroll
            for (int mt = 0; mt < 2; mt++)
                ldmat4(a[mt], sA2 + (wm + mt * 16 + (lane & 15)) * P2 + k0 + (lane >> 4) * 8);
#pragma unroll
            for (int pr = 0; pr < 2; pr++) {
                uint32_t r4[4];
                ldmat4(r4, sW2 + (wn + pr * 16 + (lane >> 4) * 8 + (lane & 7)) * P2
                             + k0 + ((lane >> 3) & 1) * 8);
                b[2 * pr][0] = r4[0]; b[2 * pr][1] = r4[1];
                b[2 * pr + 1][0] = r4[2]; b[2 * pr + 1][1] = r4[3];
            }
#pragma unroll
            for (int mt = 0; mt < 2; mt++)
#pragma unroll
                for (int nt = 0; nt < 4; nt++) mma16816(acc[mt][nt], a[mt], b[nt]);
        }
#pragma unroll
        for (int mt = 0; mt < 2; mt++) {
            int row = wm + mt * 16 + (lane >> 2);
            float dva = rsqrtf((float)g_cursor[n0 + row] + 1.0f) * Z2SCALE;
            float dvb = rsqrtf((float)g_cursor[n0 + row + 8] + 1.0f) * Z2SCALE;
#pragma unroll
            for (int nt = 0; nt < 4; nt++) {
                int col = wn + nt * 8 + (lane & 3) * 2;
                g_z28[(size_t)(n0 + row) * 64 + (col >> 1)] =
                    float2_to_fp8x2(acc[mt][nt][0] * dva, acc[mt][nt][1] * dva);
                g_z28[(size_t)(n0 + row + 8) * 64 + (col >> 1)] =
                    float2_to_fp8x2(acc[mt][nt][2] * dvb, acc[mt][nt][3] * dvb);
            }
        }
    }
}

// ---------------- decode: agg2 + barrier + dynamically-scheduled fp8 tiles ------
__device__ __forceinline__ float sigmoidf_(float v) {
    float th;
    asm("tanh.approx.f32 %0, %1;" : "=f"(th) : "f"(v * SIGSCALE));
    return fmaf(th, 0.5f, 0.5f);
}

__device__ __forceinline__ void bulk_store_row(void* gptr, uint32_t saddr, int bytes) {
    asm volatile("cp.async.bulk.global.shared::cta.bulk_group [%0], [%1], %2;"
                 :: "l"(gptr), "r"(saddr), "r"(bytes) : "memory");
}

__device__ __forceinline__ void tile_coords(int idx, int& bi, int& bj) {
    float fb = 64.5f - sqrtf(64.5f * 64.5f - 2.0f * (float)idx);
    int b = (int)fb;
    if (b < 0) b = 0;
    while (b > 0 && (b * 64 - b * (b - 1) / 2) > idx) b--;
    while (((b + 1) * 64 - (b + 1) * b / 2) <= idx) b++;
    bi = b;
    bj = b + (idx - (b * 64 - b * (b - 1) / 2));
}

static constexpr int STG_SZ   = 128 * 136 * 4;      // 69632
static constexpr int ZB_OFF   = STG_SZ;
static constexpr int ZT_SZ    = 128 * 144;          // 18432
static constexpr int DEC_SMEM = STG_SZ + 2 * ZT_SZ; // 106496 -> 2 CTAs/SM

__global__ void __launch_bounds__(256, 2) k_decode(const float* __restrict__ bias,
                                                   float* __restrict__ out) {
    extern __shared__ char smb[];
    __shared__ unsigned s_base;
    __shared__ int s_tile;
    int t = threadIdx.x;
    int lane = t & 31, w = t >> 5;
    int wm = (w & 3) * 32;
    int wn = (w >> 2) * 64;
    constexpr int PU = 72;
    constexpr int PF = 136;

    // ---- phase 0: layer-2 aggregation (warp-per-node, strided) ----
    {
        int* sidx = (int*)smb + w * PAD;           // staging in sf area
        float4 bb = *(const float4*)(bias + lane * 4);
        for (int d = blockIdx.x * 8 + w; d < NN; d += DGRID * 8) {
            int cnt = g_cursor[d];
            const int* rowp = g_src + d * PAD;
            for (int i = lane; i < cnt; i += 32) sidx[i] = rowp[i];
            __syncwarp();
            float r0, r1, r2, r3, dd;
            agg_sum((const uint32_t*)g_z28, sidx, cnt, d, lane, r0, r1, r2, r3, dd);
            float k = dd * (ZSCALE / Z2SCALE);
            float o0 = fmaf(r0, k, bb.x * ZSCALE);
            float o1 = fmaf(r1, k, bb.y * ZSCALE);
            float o2 = fmaf(r2, k, bb.z * ZSCALE);
            float o3 = fmaf(r3, k, bb.w * ZSCALE);
            uint16_t p0 = float2_to_fp8x2(o0, o1);
            uint16_t p1 = float2_to_fp8x2(o2, o3);
            ((uint32_t*)g_z8)[d * 32 + lane] = (uint32_t)p0 | ((uint32_t)p1 << 16);
            __syncwarp();
        }
    }

    // ---- grid barrier; also derive launch index for the ticket base ----
    __syncthreads();
    if (t == 0) {
        __threadfence();
        unsigned tk = atomicAdd(&g_bar, 1u);
        unsigned target = tk - (tk % DGRID) + DGRID;
        volatile unsigned* p = &g_bar;
        while (*p < target) { __nanosleep(64); }
        unsigned L = target / DGRID - 1u;              // launch index
        s_base = L * (unsigned)(NTILES + DGRID);       // ticket base this launch
    }
    __syncthreads();
    __threadfence();
    unsigned base = s_base;

    // reset CSR cursors for the next replay (safe: all agg reads done)
    if (blockIdx.x < 32) g_cursor[blockIdx.x * 256 + t] = 0;

    float* sf = (float*)smb;
    const __nv_bfloat16* zA = (const __nv_bfloat16*)(smb + ZB_OFF);
    const __nv_bfloat16* zB = zA + ZT_SZ / 2;

    // ---- dynamically scheduled tile loop (exactly NTILES+DGRID grabs/launch) ----
    for (;;) {
        __syncthreads();   // previous iteration fully done with s_tile / smem
        if (t == 0) s_tile = (int)(atomicAdd(&g_tk, 1u) - base);
        __syncthreads();
        int idx = s_tile;
        if (idx >= NTILES) break;

        int bi, bj;
        tile_coords(idx, bi, bj);
        int i0 = bi * 128, j0 = bj * 128;
        bool diag = (bi == bj);

        {
            const char* Z = (const char*)g_z8;
#pragma unroll
            for (int k = 0; k < 8; k++) {
                int v = t + k * 256;
                int which = v >> 10;
                int r = (v >> 3) & 127;
                int c = (v & 7) * 16;
                const char* srcp = Z + (((size_t)((which ? j0 : i0) + r)) << 7) + c;
                uint32_t dstp = smem_u32(smb + ZB_OFF + which * ZT_SZ + r * 144 + c);
                asm volatile("cp.async.cg.shared.global [%0], [%1], 16;"
                             :: "r"(dstp), "l"(srcp) : "memory");
            }
        }
        asm volatile("cp.async.commit_group;" ::: "memory");
        asm volatile("cp.async.wait_group 0;" ::: "memory");
        __syncthreads();

        float acc[2][8][4] = {};
#pragma unroll
        for (int ks = 0; ks < 4; ks++) {
            int k0 = ks * 16;
            uint32_t a[2][4], b[8][2];
#pragma unroll
            for (int mt = 0; mt < 2; mt++)
                ldmat4(a[mt], zA + (wm + mt * 16 + (lane & 15)) * PU + k0 + (lane >> 4) * 8);
#pragma unroll
            for (int pr = 0; pr < 4; pr++) {
                uint32_t r4[4];
                ldmat4(r4, zB + (wn + pr * 16 + (lane >> 4) * 8 + (lane & 7)) * PU
                             + k0 + ((lane >> 3) & 1) * 8);
                b[2 * pr][0] = r4[0]; b[2 * pr][1] = r4[1];
                b[2 * pr + 1][0] = r4[2]; b[2 * pr + 1][1] = r4[3];
            }
#pragma unroll
            for (int mt = 0; mt < 2; mt++)
#pragma unroll
                for (int nt = 0; nt < 8; nt++) mma16832f8(acc[mt][nt], a[mt], b[nt]);
        }

#pragma unroll
        for (int mt = 0; mt < 2; mt++)
#pragma unroll
            for (int nt = 0; nt < 8; nt++)
#pragma unroll
                for (int q = 0; q < 4; q++) acc[mt][nt][q] = sigmoidf_(acc[mt][nt][q]);

        int r0b = wm + (lane >> 2);

        // pass 1: direct tile
        asm volatile("cp.async.bulk.wait_group.read 0;" ::: "memory");
        __syncthreads();
#pragma unroll
        for (int mt = 0; mt < 2; mt++) {
            int r0 = r0b + mt * 16;
#pragma unroll
            for (int nt = 0; nt < 8; nt++) {
                int c0 = wn + nt * 8 + (lane & 3) * 2;
                *(float2*)&sf[r0 * PF + c0] =
                    make_float2(acc[mt][nt][0], acc[mt][nt][1]);
                *(float2*)&sf[(r0 + 8) * PF + c0] =
                    make_float2(acc[mt][nt][2], acc[mt][nt][3]);
            }
        }
        __syncthreads();
        if (t < 128) {
            asm volatile("fence.proxy.async.shared::cta;" ::: "memory");
            bulk_store_row(out + (size_t)(i0 + t) * NN + j0, smem_u32(&sf[t * PF]), 512);
            asm volatile("cp.async.bulk.commit_group;" ::: "memory");
        }

        // pass 2: mirror tile (transposed)
        if (!diag) {
            asm volatile("cp.async.bulk.wait_group.read 0;" ::: "memory");
            __syncthreads();
#pragma unroll
            for (int mt = 0; mt < 2; mt++) {
                int r0 = r0b + mt * 16;
#pragma unroll
                for (int nt = 0; nt < 8; nt++) {
                    int c0 = wn + nt * 8 + (lane & 3) * 2;
                    sf[c0 * PF + r0]           = acc[mt][nt][0];
                    sf[(c0 + 1) * PF + r0]     = acc[mt][nt][1];
                    sf[c0 * PF + r0 + 8]       = acc[mt][nt][2];
                    sf[(c0 + 1) * PF + r0 + 8] = acc[mt][nt][3];
                }
            }
            __syncthreads();
            if (t < 128) {
                asm volatile("fence.proxy.async.shared::cta;" ::: "memory");
                bulk_store_row(out + (size_t)(j0 + t) * NN + i0, smem_u32(&sf[t * PF]), 512);
                asm volatile("cp.async.bulk.commit_group;" ::: "memory");
            }
        }
    }

    asm volatile("cp.async.bulk.wait_group 0;" ::: "memory");
}

// ---------------- launch ----------------------------------------------------------
extern "C" void kernel_launch(void* const* d_in, const int* in_sizes, int n_in,
                              void* d_out, int out_size) {
    const int*   x   = (const int*)d_in[0];
    const int*   ei  = (const int*)d_in[1];
    const float* emb = (const float*)d_in[2];
    const float* W1  = (const float*)d_in[3];
    const float* b1  = (const float*)d_in[4];
    const float* W2  = (const float*)d_in[5];
    const float* b2  = (const float*)d_in[6];
    float* out = (float*)d_out;

    const int* src = ei;
    const int* dst = ei + EE;

    cudaFuncSetAttribute(k_decode, cudaFuncAttributeMaxDynamicSharedMemorySize, DEC_SMEM);
    cudaFuncSetAttribute(k_lin,    cudaFuncAttributeMaxDynamicSharedMemorySize, LIN_SMEM);

    k_prep  <<<512, 256>>>(W1, W2, src, dst);
    k_gather<<<NN * 64 / 256, 256>>>(x, emb);
    k_agg0  <<<NN, 32>>>();
    k_lin   <<<NN / 64, 256, LIN_SMEM>>>(b1);
    k_decode<<<DGRID, 256, DEC_SMEM>>>(b2, out);
}